// round 8
// baseline (speedup 1.0000x reference)
#include <cuda_runtime.h>
#include <cuda_fp16.h>
#include <cstdint>
#include <cstddef>

// ============================================================================
// Problem constants. Harness dtypes: x/SCB/bias = float32 (fp16 values upcast
// losslessly), CB = int32, output = float32.
// ============================================================================
static constexpr int D_IN   = 4096;
static constexpr int D_OUT  = 11008;
static constexpr int M_TOT  = 8192;                 // 4 * 2048
static constexpr int BM     = 128;
static constexpr int BN     = 128;
static constexpr int BK     = 64;                   // halves per stage (128 B rows)
static constexpr int KITERS = D_IN / BK;            // 64
static constexpr int TILES_M = M_TOT / BM;          // 64
static constexpr int TILES_N = D_OUT / BN;          // 86
static constexpr int N_TILES = TILES_M * TILES_N;   // 5504
static constexpr int A_BYTES = BM * BK * 2;         // 16 KB
static constexpr int STAGE_BYTES = (BM + BN) * BK * 2;  // 32 KB
static constexpr int SMEM_BYTES  = 3 * STAGE_BYTES + 1024; // 97 KB (pad for 1K align)
static constexpr int GRID = 304;                    // 2 CTAs/SM x 152 SMs (GB300)

// Device-global scratch (allocation-free): fp16 copies of x and dequantized W
__device__ __align__(16) __half g_X[(size_t)M_TOT * D_IN];   // 64 MB
__device__ __align__(16) __half g_W[(size_t)D_OUT * D_IN];   // 90 MB

// ============================================================================
// Helpers
// ============================================================================
__device__ __forceinline__ uint32_t smem_u32(const void* p) {
    uint32_t a;
    asm("{ .reg .u64 t; cvta.to.shared.u64 t, %1; cvt.u32.u64 %0, t; }"
        : "=r"(a) : "l"(p));
    return a;
}

__device__ __forceinline__ void cp_async16(uint32_t dst, const void* src) {
    asm volatile("cp.async.cg.shared.global [%0], [%1], 16;"
                 :: "r"(dst), "l"(src) : "memory");
}
#define CP_COMMIT() asm volatile("cp.async.commit_group;" ::: "memory")
#define CP_WAIT1()  asm volatile("cp.async.wait_group 1;" ::: "memory")

// ============================================================================
// Kernel 1 (merged prep): x fp32->fp16 AND dequant CB int32 -> W fp16.
// Dequant matches reference fp16 chain: s = fp16(SCB)/fp16(127); W = fp16(CB)*s.
// ============================================================================
static constexpr size_t NX_VEC = (size_t)M_TOT * D_IN / 8;     // 4,194,304
static constexpr size_t NW_VEC = (size_t)D_OUT * D_IN / 8;     // 5,636,096
static constexpr int PREP_BLOCKS = (int)((NX_VEC + NW_VEC) / 256);  // 38400

__global__ __launch_bounds__(256) void prep_kernel(const float* __restrict__ xf,
                                                   const int* __restrict__ CB,
                                                   const float* __restrict__ SCB) {
    size_t i = (size_t)blockIdx.x * 256 + threadIdx.x;
    if (i < NX_VEC) {
        const float4* p = (const float4*)xf + i * 2;
        float4 a = p[0], b = p[1];
        union { uint4 v; __half2 h[4]; } u;
        u.h[0] = __floats2half2_rn(a.x, a.y);
        u.h[1] = __floats2half2_rn(a.z, a.w);
        u.h[2] = __floats2half2_rn(b.x, b.y);
        u.h[3] = __floats2half2_rn(b.z, b.w);
        ((uint4*)g_X)[i] = u.v;
    } else {
        size_t j = i - NX_VEC;
        int n = (int)(j >> 9);                           // (j*8)/4096
        __half s = __hdiv(__float2half_rn(SCB[n]), __float2half(127.0f));
        const int4* p = (const int4*)CB + j * 2;
        int4 a = p[0], b = p[1];
        union { uint4 v; __half2 h[4]; } u;
        u.h[0] = __halves2half2(__hmul(__int2half_rn(a.x), s), __hmul(__int2half_rn(a.y), s));
        u.h[1] = __halves2half2(__hmul(__int2half_rn(a.z), s), __hmul(__int2half_rn(a.w), s));
        u.h[2] = __halves2half2(__hmul(__int2half_rn(b.x), s), __hmul(__int2half_rn(b.y), s));
        u.h[3] = __halves2half2(__hmul(__int2half_rn(b.z), s), __hmul(__int2half_rn(b.w), s));
        ((uint4*)g_W)[j] = u.v;
    }
}

// ============================================================================
// Kernel 2: persistent-CTA mma.sync fp16 GEMM. CTA 128x128x64, 4 warps (2x2),
// warp tile 64x64, 3-stage cp.async ring that flows CONTINUOUSLY across tile
// boundaries (prefetch at k=62/63 targets next tile's k=0/1); epilogue of tile
// t overlaps the in-flight loads of tile t+1. 2 CTAs/SM.
//
// SW128 swizzle: sw(row, cb) = row*128 + (cb ^ ((row&7)<<4)).
// Per-ks address trick: stage bases 1024-aligned, kb ∈ {0,32,64,96} lives in
// bits 5-6 -> addr(ks) = (stage_base + tile_const) ^ kb.
// ============================================================================
__device__ __forceinline__ void tile_coords(int t, int& m0, int& n0) {
    // Grouped raster: 8 m-tiles per supergroup, n fastest (B stays in L2)
    const int per = 8 * TILES_N;
    int g = t / per;
    int r = t % per;
    m0 = (g * 8 + (r & 7)) * BM;
    n0 = (r >> 3) * BN;
}

__device__ __forceinline__ void load_stage(uint32_t base, int m0, int n0, int k0,
                                           int tid) {
    int r = tid >> 3;            // 0..15
    int c = tid & 7;             // 16B chunk in row
    uint32_t cbx = (uint32_t)(c * 16) ^ (uint32_t)((r & 7) << 4);
#pragma unroll
    for (int i = 0; i < 8; ++i) {                       // A rows r, r+16, ...
        int rr = r + i * 16;
        cp_async16(base + (uint32_t)rr * 128 + cbx,
                   g_X + (size_t)(m0 + rr) * D_IN + k0 + c * 8);
    }
    uint32_t bbase = base + A_BYTES;
#pragma unroll
    for (int i = 0; i < 8; ++i) {                       // B rows r, r+16, ...
        int rr = r + i * 16;
        cp_async16(bbase + (uint32_t)rr * 128 + cbx,
                   g_W + (size_t)(n0 + rr) * D_IN + k0 + c * 8);
    }
}

__device__ __forceinline__ void ld_frags(uint32_t sa, uint32_t kb,
                                         const uint32_t ta[4], const uint32_t tb[4],
                                         uint32_t RA[4][4], uint32_t RB[4][4]) {
#pragma unroll
    for (int mt = 0; mt < 4; ++mt) {
        uint32_t addr = (sa + ta[mt]) ^ kb;
        asm volatile("ldmatrix.sync.aligned.m8n8.x4.shared.b16 {%0,%1,%2,%3}, [%4];"
            : "=r"(RA[mt][0]), "=r"(RA[mt][1]), "=r"(RA[mt][2]), "=r"(RA[mt][3])
            : "r"(addr));
    }
#pragma unroll
    for (int p = 0; p < 4; ++p) {
        uint32_t addr = (sa + tb[p]) ^ kb;
        asm volatile("ldmatrix.sync.aligned.m8n8.x4.shared.b16 {%0,%1,%2,%3}, [%4];"
            : "=r"(RB[p][0]), "=r"(RB[p][1]), "=r"(RB[p][2]), "=r"(RB[p][3])
            : "r"(addr));
    }
}

__global__ __launch_bounds__(128, 2)
void gemm_kernel(const float* __restrict__ biasf,
                 float* __restrict__ out) {
    extern __shared__ char smem[];
    uint32_t sbA = (smem_u32(smem) + 1023u) & ~1023u;   // 1K-aligned stage base
    int tid  = threadIdx.x;
    int lane = tid & 31;
    int wid  = tid >> 5;         // 0..3
    int warp_m = wid >> 1;       // 0..1 (64 rows each)
    int warp_n = wid & 1;        // 0..1 (64 cols each)

    // Tile constants: toff = row*128 + (colbase ^ ((row&7)<<4))
    uint32_t ta[4], tb[4];
    {
        uint32_t acb = (uint32_t)((lane >> 4) * 16);
        uint32_t bcb = (uint32_t)(((lane >> 3) & 1) * 16);
#pragma unroll
        for (int mt = 0; mt < 4; ++mt) {
            int row = warp_m * 64 + mt * 16 + ((lane >> 3) & 1) * 8 + (lane & 7);
            ta[mt] = (uint32_t)row * 128 + (acb ^ (uint32_t)((row & 7) << 4));
        }
#pragma unroll
        for (int p = 0; p < 4; ++p) {
            int row = warp_n * 64 + p * 16 + ((lane >> 4) * 8) + (lane & 7);
            tb[p] = (uint32_t)A_BYTES + (uint32_t)row * 128 +
                    (bcb ^ (uint32_t)((row & 7) << 4));
        }
    }

    // Persistent tile schedule: t, t+GRID, t+2*GRID, ...
    int t_cur = blockIdx.x;
    int m0, n0;
    tile_coords(t_cur, m0, n0);
    int t_nxt = t_cur + GRID;
    bool has_next = (t_nxt < N_TILES);
    int m0n = 0, n0n = 0;
    if (has_next) tile_coords(t_nxt, m0n, n0n);

    uint32_t s0 = sbA, s1 = sbA + STAGE_BYTES, s2 = sbA + 2 * STAGE_BYTES;

    float acc[4][8][4];
#pragma unroll
    for (int i = 0; i < 4; ++i)
#pragma unroll
        for (int j = 0; j < 8; ++j)
#pragma unroll
            for (int q = 0; q < 4; ++q) acc[i][j][q] = 0.0f;

    uint32_t RA[2][4][4], RB[2][4][4];

    // Prologue: fill stages 0,1 of first tile; load frags(k=0)
    load_stage(s0, m0, n0, 0, tid);  CP_COMMIT();
    load_stage(s1, m0, n0, BK, tid); CP_COMMIT();
    CP_WAIT1();
    __syncthreads();
    ld_frags(s0, 0, ta, tb, RA[0], RB[0]);

    while (true) {
#pragma unroll 1
        for (int k = 0; k < KITERS; ++k) {
#pragma unroll
            for (int ks = 0; ks < 4; ++ks) {
                const int cur = ks & 1;
                const int nxt = cur ^ 1;

                if (ks < 2) {
                    // frags(k, ks+1) — covered by this ks's 32 MMAs
                    ld_frags(s0, (uint32_t)((ks + 1) * 32), ta, tb, RA[nxt], RB[nxt]);
                } else if (ks == 2) {
                    // frags(k,3) first (critical LDSM ahead of LDGSTS burst)
                    ld_frags(s0, 96u, ta, tb, RA[nxt], RB[nxt]);
                    if (k < KITERS - 2) {
                        load_stage(s2, m0, n0, (k + 2) * BK, tid);
                    } else if (has_next) {
                        // cross-tile prefetch: next tile's k = k-62 in {0,1}
                        load_stage(s2, m0n, n0n, (k - (KITERS - 2)) * BK, tid);
                    }
                    CP_COMMIT();   // unconditional: uniform wait_group counts
                } else {           // ks == 3
                    bool last_all = (!has_next) && (k == KITERS - 1);
                    if (!last_all) {
                        CP_WAIT1();          // 2nd-newest group (next stage) landed
                        __syncthreads();     // hidden by in-flight MMA backlog
                        ld_frags(s1, 0, ta, tb, RA[nxt], RB[nxt]);
                    }
                }

#pragma unroll
                for (int mt = 0; mt < 4; ++mt)
#pragma unroll
                    for (int nt = 0; nt < 8; ++nt) {
                        uint32_t b0 = RB[cur][nt >> 1][(nt & 1) * 2];
                        uint32_t b1 = RB[cur][nt >> 1][(nt & 1) * 2 + 1];
                        asm volatile(
                            "mma.sync.aligned.m16n8k16.row.col.f32.f16.f16.f32 "
                            "{%0,%1,%2,%3}, {%4,%5,%6,%7}, {%8,%9}, {%0,%1,%2,%3};"
                            : "+f"(acc[mt][nt][0]), "+f"(acc[mt][nt][1]),
                              "+f"(acc[mt][nt][2]), "+f"(acc[mt][nt][3])
                            : "r"(RA[cur][mt][0]), "r"(RA[cur][mt][1]),
                              "r"(RA[cur][mt][2]), "r"(RA[cur][mt][3]),
                              "r"(b0), "r"(b1));
                    }
            }
            // rotate stage ring
            uint32_t tmp = s0; s0 = s1; s1 = s2; s2 = tmp;
        }

        // Epilogue for tile (m0, n0): fp16(acc)+fp16(bias), upcast to fp32.
        // Overlaps next tile's in-flight cp.async stages.
        {
            int t2 = (lane & 3) * 2;
            int gg = lane >> 2;
#pragma unroll
            for (int nt = 0; nt < 8; ++nt) {
                int col = n0 + warp_n * 64 + nt * 8 + t2;
                float2 bf = *(const float2*)(biasf + col);
                __half blo = __float2half_rn(bf.x);
                __half bhi = __float2half_rn(bf.y);
#pragma unroll
                for (int mt = 0; mt < 4; ++mt) {
                    int row0 = m0 + warp_m * 64 + mt * 16 + gg;
                    float2 v0 = make_float2(
                        __half2float(__hadd(__float2half_rn(acc[mt][nt][0]), blo)),
                        __half2float(__hadd(__float2half_rn(acc[mt][nt][1]), bhi)));
                    *(float2*)(out + (size_t)row0 * D_OUT + col) = v0;
                    float2 v1 = make_float2(
                        __half2float(__hadd(__float2half_rn(acc[mt][nt][2]), blo)),
                        __half2float(__hadd(__float2half_rn(acc[mt][nt][3]), bhi)));
                    *(float2*)(out + (size_t)(row0 + 8) * D_OUT + col) = v1;
                }
            }
        }

        if (!has_next) break;

        // Advance to next tile; reset accumulators
        m0 = m0n; n0 = n0n;
        t_nxt += GRID;
        has_next = (t_nxt < N_TILES);
        if (has_next) tile_coords(t_nxt, m0n, n0n);
#pragma unroll
        for (int i = 0; i < 4; ++i)
#pragma unroll
            for (int j = 0; j < 8; ++j)
#pragma unroll
                for (int q = 0; q < 4; ++q) acc[i][j][q] = 0.0f;
    }
}

// ============================================================================
// Launch
// ============================================================================
extern "C" void kernel_launch(void* const* d_in, const int* in_sizes, int n_in,
                              void* d_out, int out_size) {
    const float* x    = (const float*)d_in[0];
    const int*   CB   = (const int*)d_in[1];
    const float* SCB  = (const float*)d_in[2];
    const float* bias = (const float*)d_in[3];
    float* out = (float*)d_out;

    // 1) Merged prep: x->fp16 and W dequant
    prep_kernel<<<PREP_BLOCKS, 256>>>(x, CB, SCB);

    // 2) Persistent tensor-core GEMM (legacy mma.sync — tcgen05 blocked by the
    //    harness's compute_103 virtual-arch compile), 2 CTAs/SM, continuous
    //    cross-tile cp.async pipeline.
    cudaFuncSetAttribute(gemm_kernel, cudaFuncAttributeMaxDynamicSharedMemorySize,
                         SMEM_BYTES);
    gemm_kernel<<<GRID, 128, SMEM_BYTES>>>(bias, out);
}

// round 9
// speedup vs baseline: 1.0314x; 1.0314x over previous
#include <cuda_runtime.h>
#include <cuda_fp16.h>
#include <cstdint>
#include <cstddef>

// ============================================================================
// Problem constants. Harness dtypes: x/SCB/bias = float32 (fp16 values upcast
// losslessly), CB = int32, output = float32.
// ============================================================================
static constexpr int D_IN   = 4096;
static constexpr int D_OUT  = 11008;
static constexpr int M_TOT  = 8192;                 // 4 * 2048
static constexpr int BM     = 128;
static constexpr int BN     = 128;
static constexpr int BK     = 64;                   // halves per stage (128 B rows)
static constexpr int KITERS = D_IN / BK;            // 64
static constexpr int STAGES = 3;
static constexpr int TILES_M = M_TOT / BM;          // 64
static constexpr int TILES_N = D_OUT / BN;          // 86
static constexpr int A_BYTES = BM * BK * 2;         // 16 KB
static constexpr int STAGE_BYTES = (BM + BN) * BK * 2;  // 32 KB
static constexpr int SMEM_BYTES  = STAGES * STAGE_BYTES + 1024; // 97 KB

// Device-global scratch (allocation-free): fp16 copies of x and dequantized W
__device__ __align__(16) __half g_X[(size_t)M_TOT * D_IN];   // 64 MB
__device__ __align__(16) __half g_W[(size_t)D_OUT * D_IN];   // 90 MB

// ============================================================================
// Helpers
// ============================================================================
__device__ __forceinline__ uint32_t smem_u32(const void* p) {
    uint32_t a;
    asm("{ .reg .u64 t; cvta.to.shared.u64 t, %1; cvt.u32.u64 %0, t; }"
        : "=r"(a) : "l"(p));
    return a;
}

__device__ __forceinline__ void cp_async16(uint32_t dst, const void* src) {
    asm volatile("cp.async.cg.shared.global [%0], [%1], 16;"
                 :: "r"(dst), "l"(src) : "memory");
}
#define CP_COMMIT() asm volatile("cp.async.commit_group;" ::: "memory")
#define CP_WAIT1()  asm volatile("cp.async.wait_group 1;" ::: "memory")

// Named split barriers (128 arrive-only + 128 sync = 256 per phase)
#define BAR_A_SYNC()   asm volatile("bar.sync 1, 256;" ::: "memory")
#define BAR_A_ARRIVE() asm volatile("bar.arrive 1, 256;" ::: "memory")
#define BAR_V_SYNC()   asm volatile("bar.sync 2, 256;" ::: "memory")
#define BAR_V_ARRIVE() asm volatile("bar.arrive 2, 256;" ::: "memory")

// ============================================================================
// Kernel 1 (merged prep): x fp32->fp16 AND dequant CB int32 -> W fp16.
// Dequant matches reference fp16 chain: s = fp16(SCB)/fp16(127); W = fp16(CB)*s.
// ============================================================================
static constexpr size_t NX_VEC = (size_t)M_TOT * D_IN / 8;     // 4,194,304
static constexpr size_t NW_VEC = (size_t)D_OUT * D_IN / 8;     // 5,636,096
static constexpr int PREP_BLOCKS = (int)((NX_VEC + NW_VEC) / 256);  // 38400

__global__ __launch_bounds__(256) void prep_kernel(const float* __restrict__ xf,
                                                   const int* __restrict__ CB,
                                                   const float* __restrict__ SCB) {
    size_t i = (size_t)blockIdx.x * 256 + threadIdx.x;
    if (i < NX_VEC) {
        const float4* p = (const float4*)xf + i * 2;
        float4 a = p[0], b = p[1];
        union { uint4 v; __half2 h[4]; } u;
        u.h[0] = __floats2half2_rn(a.x, a.y);
        u.h[1] = __floats2half2_rn(a.z, a.w);
        u.h[2] = __floats2half2_rn(b.x, b.y);
        u.h[3] = __floats2half2_rn(b.z, b.w);
        ((uint4*)g_X)[i] = u.v;
    } else {
        size_t j = i - NX_VEC;
        int n = (int)(j >> 9);                           // (j*8)/4096
        __half s = __hdiv(__float2half_rn(SCB[n]), __float2half(127.0f));
        const int4* p = (const int4*)CB + j * 2;
        int4 a = p[0], b = p[1];
        union { uint4 v; __half2 h[4]; } u;
        u.h[0] = __halves2half2(__hmul(__int2half_rn(a.x), s), __hmul(__int2half_rn(a.y), s));
        u.h[1] = __halves2half2(__hmul(__int2half_rn(a.z), s), __hmul(__int2half_rn(a.w), s));
        u.h[2] = __halves2half2(__hmul(__int2half_rn(b.x), s), __hmul(__int2half_rn(b.y), s));
        u.h[3] = __halves2half2(__hmul(__int2half_rn(b.z), s), __hmul(__int2half_rn(b.w), s));
        ((uint4*)g_W)[j] = u.v;
    }
}

// ============================================================================
// Kernel 2: mma.sync fp16 GEMM. CTA 128x128x64, 4 warps (2x2), warp tile 64x64,
// 3-stage cp.async pipeline, 2 CTAs/SM, register-double-buffered fragments.
// Split named barriers instead of __syncthreads:
//   B_V (visibility): arrive@ks2 after wait_group; sync@ks3 before reading the
//       next stage (producers' waits happen-before consumers' reads).
//   B_A (anti-dep): arrive@ks2 after the LAST read (kb=96) of the recycled
//       stage; sync@next-iter ks2 before overwriting it (1 full iter of slack).
// SW128 swizzle: sw(row, cb) = row*128 + (cb ^ ((row&7)<<4)); per-ks address
// trick: kb ∈ {0,32,64,96} -> addr(ks) = (stage_base + tile_const) ^ kb.
// ============================================================================
__device__ __forceinline__ void load_stage(int m0, int n0, int k,
                                           uint32_t sbA, int tid) {
    uint32_t base = sbA + (uint32_t)(k % STAGES) * STAGE_BYTES;
    int k0 = k * BK;
    int r = tid >> 3;            // 0..15
    int c = tid & 7;             // 16B chunk in row
    uint32_t cbx = (uint32_t)(c * 16) ^ (uint32_t)((r & 7) << 4);
#pragma unroll
    for (int i = 0; i < 8; ++i) {                       // A rows r, r+16, ...
        int rr = r + i * 16;
        cp_async16(base + (uint32_t)rr * 128 + cbx,
                   g_X + (size_t)(m0 + rr) * D_IN + k0 + c * 8);
    }
    uint32_t bbase = base + A_BYTES;
#pragma unroll
    for (int i = 0; i < 8; ++i) {                       // B rows r, r+16, ...
        int rr = r + i * 16;
        cp_async16(bbase + (uint32_t)rr * 128 + cbx,
                   g_W + (size_t)(n0 + rr) * D_IN + k0 + c * 8);
    }
}

__device__ __forceinline__ void ld_frags(uint32_t sa, uint32_t kb,
                                         const uint32_t ta[4], const uint32_t tb[4],
                                         uint32_t RA[4][4], uint32_t RB[4][4]) {
#pragma unroll
    for (int mt = 0; mt < 4; ++mt) {
        uint32_t addr = (sa + ta[mt]) ^ kb;
        asm volatile("ldmatrix.sync.aligned.m8n8.x4.shared.b16 {%0,%1,%2,%3}, [%4];"
            : "=r"(RA[mt][0]), "=r"(RA[mt][1]), "=r"(RA[mt][2]), "=r"(RA[mt][3])
            : "r"(addr));
    }
#pragma unroll
    for (int p = 0; p < 4; ++p) {
        uint32_t addr = (sa + tb[p]) ^ kb;
        asm volatile("ldmatrix.sync.aligned.m8n8.x4.shared.b16 {%0,%1,%2,%3}, [%4];"
            : "=r"(RB[p][0]), "=r"(RB[p][1]), "=r"(RB[p][2]), "=r"(RB[p][3])
            : "r"(addr));
    }
}

__global__ __launch_bounds__(128, 2)
void gemm_kernel(const float* __restrict__ biasf,
                 float* __restrict__ out) {
    extern __shared__ char smem[];
    uint32_t sbA = (smem_u32(smem) + 1023u) & ~1023u;   // 1K-aligned stage base
    int tid  = threadIdx.x;
    int lane = tid & 31;
    int wid  = tid >> 5;         // 0..3
    int warp_m = wid >> 1;       // 0..1 (64 rows each)
    int warp_n = wid & 1;        // 0..1 (64 cols each)

    // Grouped rasterization: 8 m-tiles per supergroup, n fastest (B stays in L2)
    const int per = 8 * TILES_N;
    int g  = blockIdx.x / per;
    int r  = blockIdx.x % per;
    int mi = g * 8 + (r & 7);
    int ni = r >> 3;
    int m0 = mi * BM;
    int n0 = ni * BN;

    // Tile constants: toff = row*128 + (colbase ^ ((row&7)<<4))
    uint32_t ta[4], tb[4];
    {
        uint32_t acb = (uint32_t)((lane >> 4) * 16);
        uint32_t bcb = (uint32_t)(((lane >> 3) & 1) * 16);
#pragma unroll
        for (int mt = 0; mt < 4; ++mt) {
            int row = warp_m * 64 + mt * 16 + ((lane >> 3) & 1) * 8 + (lane & 7);
            ta[mt] = (uint32_t)row * 128 + (acb ^ (uint32_t)((row & 7) << 4));
        }
#pragma unroll
        for (int p = 0; p < 4; ++p) {
            int row = warp_n * 64 + p * 16 + ((lane >> 4) * 8) + (lane & 7);
            tb[p] = (uint32_t)A_BYTES + (uint32_t)row * 128 +
                    (bcb ^ (uint32_t)((row & 7) << 4));
        }
    }

    float acc[4][8][4];
#pragma unroll
    for (int i = 0; i < 4; ++i)
#pragma unroll
        for (int j = 0; j < 8; ++j)
#pragma unroll
            for (int q = 0; q < 4; ++q) acc[i][j][q] = 0.0f;

    uint32_t RA[2][4][4], RB[2][4][4];

    // Prologue: fill stages 0,1; wait stage 0; load frags(0, ks=0); prime B_A.
    load_stage(m0, n0, 0, sbA, tid); CP_COMMIT();
    load_stage(m0, n0, 1, sbA, tid); CP_COMMIT();
    CP_WAIT1();
    __syncthreads();
    ld_frags(sbA, 0, ta, tb, RA[0], RB[0]);
    BAR_A_ARRIVE();                                    // prime anti-dep phase 0

#pragma unroll 1
    for (int k = 0; k < KITERS; ++k) {
        uint32_t sa = sbA + (uint32_t)(k % STAGES) * STAGE_BYTES;
#pragma unroll
        for (int ks = 0; ks < 4; ++ks) {
            const int cur = ks & 1;
            const int nxt = cur ^ 1;

            if (ks < 2) {
                // frags(k, ks+1) — covered by this ks's 32 MMAs
                ld_frags(sa, (uint32_t)((ks + 1) * 32), ta, tb, RA[nxt], RB[nxt]);
            } else if (ks == 2) {
                // Last read (kb=96) of the recycled stage, then overwrite guard.
                ld_frags(sa, 96u, ta, tb, RA[nxt], RB[nxt]);
                BAR_A_SYNC();      // all warps done with the stage we overwrite
                if (k + 2 < KITERS) load_stage(m0, n0, k + 2, sbA, tid);
                CP_COMMIT();       // unconditional: uniform wait_group counts
                CP_WAIT1();        // our (k+1)-stage group has landed
                BAR_V_ARRIVE();    // publish: this warp's loads are visible
                BAR_A_ARRIVE();    // this warp finished reading current stage
            } else {               // ks == 3
                if (k + 1 < KITERS) {
                    BAR_V_SYNC();  // everyone's (k+1)-stage loads visible
                    uint32_t sa2 = sbA + (uint32_t)((k + 1) % STAGES) * STAGE_BYTES;
                    ld_frags(sa2, 0, ta, tb, RA[nxt], RB[nxt]);
                }
            }

#pragma unroll
            for (int mt = 0; mt < 4; ++mt)
#pragma unroll
                for (int nt = 0; nt < 8; ++nt) {
                    uint32_t b0 = RB[cur][nt >> 1][(nt & 1) * 2];
                    uint32_t b1 = RB[cur][nt >> 1][(nt & 1) * 2 + 1];
                    asm volatile(
                        "mma.sync.aligned.m16n8k16.row.col.f32.f16.f16.f32 "
                        "{%0,%1,%2,%3}, {%4,%5,%6,%7}, {%8,%9}, {%0,%1,%2,%3};"
                        : "+f"(acc[mt][nt][0]), "+f"(acc[mt][nt][1]),
                          "+f"(acc[mt][nt][2]), "+f"(acc[mt][nt][3])
                        : "r"(RA[cur][mt][0]), "r"(RA[cur][mt][1]),
                          "r"(RA[cur][mt][2]), "r"(RA[cur][mt][3]),
                          "r"(b0), "r"(b1));
                }
        }
    }

    // Epilogue: fp16(acc_f32) + fp16(bias), then upcast to fp32 output
    int t2 = (lane & 3) * 2;
    int gg = lane >> 2;
#pragma unroll
    for (int nt = 0; nt < 8; ++nt) {
        int col = n0 + warp_n * 64 + nt * 8 + t2;
        float2 bf = *(const float2*)(biasf + col);
        __half blo = __float2half_rn(bf.x);
        __half bhi = __float2half_rn(bf.y);
#pragma unroll
        for (int mt = 0; mt < 4; ++mt) {
            int row0 = m0 + warp_m * 64 + mt * 16 + gg;
            float2 v0 = make_float2(
                __half2float(__hadd(__float2half_rn(acc[mt][nt][0]), blo)),
                __half2float(__hadd(__float2half_rn(acc[mt][nt][1]), bhi)));
            *(float2*)(out + (size_t)row0 * D_OUT + col) = v0;
            float2 v1 = make_float2(
                __half2float(__hadd(__float2half_rn(acc[mt][nt][2]), blo)),
                __half2float(__hadd(__float2half_rn(acc[mt][nt][3]), bhi)));
            *(float2*)(out + (size_t)(row0 + 8) * D_OUT + col) = v1;
        }
    }
}

// ============================================================================
// Launch
// ============================================================================
extern "C" void kernel_launch(void* const* d_in, const int* in_sizes, int n_in,
                              void* d_out, int out_size) {
    const float* x    = (const float*)d_in[0];
    const int*   CB   = (const int*)d_in[1];
    const float* SCB  = (const float*)d_in[2];
    const float* bias = (const float*)d_in[3];
    float* out = (float*)d_out;

    // 1) Merged prep: x->fp16 and W dequant
    prep_kernel<<<PREP_BLOCKS, 256>>>(x, CB, SCB);

    // 2) Tensor-core GEMM (legacy mma.sync — tcgen05 blocked by the harness's
    //    compute_103 virtual-arch compile), 2 CTAs/SM, 64x64 warp tiles,
    //    fragment double-buffering, split named barriers.
    cudaFuncSetAttribute(gemm_kernel, cudaFuncAttributeMaxDynamicSharedMemorySize,
                         SMEM_BYTES);
    gemm_kernel<<<TILES_M * TILES_N, 128, SMEM_BYTES>>>(bias, out);
}